// round 11
// baseline (speedup 1.0000x reference)
#include <cuda_runtime.h>
#include <math.h>
#include <float.h>

#define XS 2048
#define NN 4096
#define ZS 64
#define DD 6208
#define NV4 1552          // DD/4
#define TK 16
#define ZTK 8
#define EPSF 1e-9f
#define RNDF 0.5f
#define NCHUNK 64         // 32 rows per chunk
#define MIXBLK 128        // NCHUNK * 2 column-halves
#define HALF4 776         // NV4/2
#define YBLK 16
#define NCAND (YBLK * (TK + 1))   // 272

// k_main block layout
#define MVROWS 4161       // rows 2047..6207
#define TB0 (MIXBLK + MVROWS)     // 4289: tail start
#define NMAIN (TB0 + 9)           // 7 reduce + 1 combine + 1 dots

// k_post block roles
#define B_YC0   0         // 16 blocks: y candidates
#define B_Z     16        // z top-9 + finals
#define B_XM    17        // x max -> inv_dx
#define B_YM    18        // y merge
#define B_MYZ0  19        // 7 blocks: mix_y/mix_z
#define B_XU0   26        // 512 blocks: x updates
#define B_YZ0   538       // 24 blocks: yz updates
#define NPOST   562

typedef unsigned long long u64;
typedef unsigned int u32;

// ---------------- device scratch (no allocations allowed) ----------------
__device__ __align__(16) float g_resp[DD];
__device__ __align__(16) float g_mix_x[DD];
__device__ __align__(16) float g_mix_y[DD];
__device__ __align__(16) float g_mix_z[DD];
__device__ float4 g_part4[NCHUNK][NV4];     // mix_x partials
__device__ float  g_respPart[NCHUNK][2][32];// per-(chunk,half) row-dot partials
__device__ u64   g_ckey[YBLK][TK + 1];
__device__ float g_yval[TK + 1];
__device__ int   g_yrow[TK + 1];
__device__ float g_zval[ZTK + 1];
__device__ int   g_zrow[ZTK + 1];
__device__ float g_inv_dx;
__device__ float g_dots[3];                 // |mix_x|^2, mix_x.inpt, |inpt|^2
// dependency counters (reset in k_init each call)
__device__ int c_red, c_red2, c_yc, c_y, c_z, c_x, c_myz;

// ---------------- helpers ----------------
__device__ __forceinline__ float blockReduceSumB(float v) {
    __shared__ float red[32];
    __shared__ float bcast;
    int lane = threadIdx.x & 31;
    int wid  = threadIdx.x >> 5;
    int nw   = blockDim.x >> 5;
#pragma unroll
    for (int o = 16; o > 0; o >>= 1) v += __shfl_down_sync(0xffffffffu, v, o);
    if (lane == 0) red[wid] = v;
    __syncthreads();
    if (wid == 0) {
        float x = (lane < nw) ? red[lane] : 0.0f;
#pragma unroll
        for (int o = 16; o > 0; o >>= 1) x += __shfl_down_sync(0xffffffffu, x, o);
        if (lane == 0) bcast = x;
    }
    __syncthreads();
    return bcast;
}

__device__ __forceinline__ u64 makeKey(float v, int row) {
    u32 u = __float_as_uint(v);
    u = (u & 0x80000000u) ? ~u : (u | 0x80000000u);
    return ((u64)u << 32) | (u32)(~row);
}
__device__ __forceinline__ float keyVal(u64 k) {
    u32 u = (u32)(k >> 32);
    u32 bits = (u & 0x80000000u) ? (u ^ 0x80000000u) : ~u;
    return __uint_as_float(bits);
}
__device__ __forceinline__ int keyRow(u64 k) { return (int)~((u32)k); }

// inline input vector: select from x / y_response / z (all L2-hot)
__device__ __forceinline__ float4 inpt4(int c4, const float4* __restrict__ x4,
                                        const float4* __restrict__ y4,
                                        const float4* __restrict__ z4) {
    if (c4 < 512)  return __ldg(x4 + c4);
    if (c4 < 1536) return __ldg(y4 + (c4 - 512));
    return __ldg(z4 + (c4 - 1536));
}

__device__ __forceinline__ void signalCnt(int* c) {
    __threadfence();
    __syncthreads();
    if (threadIdx.x == 0) atomicAdd(c, 1);
}
__device__ __forceinline__ void waitCnt(int* c, int target) {
    if (threadIdx.x == 0) {
        while (atomicAdd(c, 0) < target) __nanosleep(64);
    }
    __syncthreads();
}

// ---------------- K1: zero finals, copy ages, reset counters ----------------
__global__ void k_init(const float* __restrict__ ages, float* __restrict__ out_z,
                       float* __restrict__ out_final, float* __restrict__ out_ages) {
    int i4 = blockIdx.x * 256 + threadIdx.x;    // 8 blocks -> 2048 threads >= 1552
    if (i4 < NV4) {
        float4 zr = {0, 0, 0, 0};
        reinterpret_cast<float4*>(out_final)[i4] = zr;
        reinterpret_cast<float4*>(out_ages)[i4]  = __ldg(((const float4*)ages) + i4);
    }
    if (blockIdx.x == 0) {
        if (threadIdx.x < 16) {
            float4 zr = {0, 0, 0, 0};
            reinterpret_cast<float4*>(out_z)[threadIdx.x] = zr;
        }
        if (threadIdx.x == 0) {
            c_red = 0; c_red2 = 0; c_yc = 0; c_y = 0; c_z = 0; c_x = 0; c_myz = 0;
        }
    }
}

// ---------------- K2: mixx+rowdots (0..127), matvec/copy (rows 2047+), tail ----------------
__global__ void k_main(const float4* __restrict__ neu4, const float* __restrict__ ages,
                       const float4* __restrict__ x4, const float4* __restrict__ y4,
                       const float4* __restrict__ z4, float* __restrict__ out_neu) {
    int t = threadIdx.x;
    int b = blockIdx.x;
    int lane = t & 31;
    int wid  = t >> 5;

    if (b < MIXBLK) {
        // ---- mix_x partials + per-row dot partials for rows [r0, r1) ----
        __shared__ float sdot[32][8];
        int chunk = b >> 1;
        int half  = b & 1;
        int r0 = chunk * 32;
        int r1 = min(r0 + 32, XS - 1);
        int cbase = half * HALF4;
        int c0 = cbase + t;
        int c1 = cbase + 256 + t;
        int c2 = cbase + 512 + t;
        int c3 = cbase + 768 + t;
        bool v3 = (768 + t) < HALF4;
        float4 i0 = inpt4(c0, x4, y4, z4);
        float4 i1 = inpt4(c1, x4, y4, z4);
        float4 i2 = inpt4(c2, x4, y4, z4);
        float4 i3 = v3 ? inpt4(c3, x4, y4, z4) : make_float4(0, 0, 0, 0);
        float4 acc0 = {0,0,0,0}, acc1 = {0,0,0,0}, acc2 = {0,0,0,0}, acc3 = {0,0,0,0};
#pragma unroll 1
        for (int r = r0; r < r1; r++) {
            float ag = __ldg(&ages[r]);
            float w = (ag - 1.0f) / ag;
            const float4* rowp = neu4 + (size_t)r * NV4;
            float4 a  = __ldg(rowp + c0);
            float4 bq = __ldg(rowp + c1);
            float4 cq = __ldg(rowp + c2);
            float4 dq = v3 ? __ldg(rowp + c3) : make_float4(0, 0, 0, 0);
            acc0.x = fmaf(w, a.x, acc0.x);  acc0.y = fmaf(w, a.y, acc0.y);
            acc0.z = fmaf(w, a.z, acc0.z);  acc0.w = fmaf(w, a.w, acc0.w);
            acc1.x = fmaf(w, bq.x, acc1.x); acc1.y = fmaf(w, bq.y, acc1.y);
            acc1.z = fmaf(w, bq.z, acc1.z); acc1.w = fmaf(w, bq.w, acc1.w);
            acc2.x = fmaf(w, cq.x, acc2.x); acc2.y = fmaf(w, cq.y, acc2.y);
            acc2.z = fmaf(w, cq.z, acc2.z); acc2.w = fmaf(w, cq.w, acc2.w);
            acc3.x = fmaf(w, dq.x, acc3.x); acc3.y = fmaf(w, dq.y, acc3.y);
            acc3.z = fmaf(w, dq.z, acc3.z); acc3.w = fmaf(w, dq.w, acc3.w);
            // row dot partial (raw row . inpt)
            float d = 0.0f;
            d = fmaf(a.x,  i0.x, d); d = fmaf(a.y,  i0.y, d);
            d = fmaf(a.z,  i0.z, d); d = fmaf(a.w,  i0.w, d);
            d = fmaf(bq.x, i1.x, d); d = fmaf(bq.y, i1.y, d);
            d = fmaf(bq.z, i1.z, d); d = fmaf(bq.w, i1.w, d);
            d = fmaf(cq.x, i2.x, d); d = fmaf(cq.y, i2.y, d);
            d = fmaf(cq.z, i2.z, d); d = fmaf(cq.w, i2.w, d);
            d = fmaf(dq.x, i3.x, d); d = fmaf(dq.y, i3.y, d);
            d = fmaf(dq.z, i3.z, d); d = fmaf(dq.w, i3.w, d);
#pragma unroll
            for (int o = 16; o > 0; o >>= 1) d += __shfl_down_sync(0xffffffffu, d, o);
            if (lane == 0) sdot[r - r0][wid] = d;
        }
        g_part4[chunk][c0] = acc0;
        g_part4[chunk][c1] = acc1;
        g_part4[chunk][c2] = acc2;
        if (v3) g_part4[chunk][c3] = acc3;
        __syncthreads();
        if (t < 32 && t < (r1 - r0)) {
            float s = 0.0f;
#pragma unroll
            for (int w2 = 0; w2 < 8; w2++) s += sdot[t][w2];
            g_respPart[chunk][half][t] = s;
        }
        signalCnt(&c_red);
        return;
    }

    if (b < TB0) {
        // ---- matvec + copy for rows 2047..6207 ----
        int row = (XS - 1) + (b - MIXBLK);
        const float4* src = neu4 + (size_t)row * NV4;
        float4* dst = reinterpret_cast<float4*>(out_neu) + (size_t)row * NV4;
        float acc = 0.0f;
#pragma unroll
        for (int j = 0; j < 7; j++) {
            int c = t + j * 256;
            if (c < NV4) {
                float4 v = __ldg(src + c);
                float4 w = inpt4(c, x4, y4, z4);
                acc = fmaf(v.x, w.x, acc);
                acc = fmaf(v.y, w.y, acc);
                acc = fmaf(v.z, w.z, acc);
                acc = fmaf(v.w, w.w, acc);
                __stcs(dst + c, v);
            }
        }
        float tot = blockReduceSumB(acc);
        if (t == 0) g_resp[row] = tot;
        return;
    }

    // ---- tail blocks ----
    int tb = b - TB0;
    if (tb < 7) {
        // mix_x reduce
        waitCnt(&c_red, MIXBLK);
        int c4 = tb * 256 + t;
        if (c4 < NV4) {
            float4 mx = {0, 0, 0, 0};
#pragma unroll
            for (int ch = 0; ch < NCHUNK; ch++) {
                float4 p = g_part4[ch][c4];
                mx.x += p.x; mx.y += p.y; mx.z += p.z; mx.w += p.w;
            }
            reinterpret_cast<float4*>(g_mix_x)[c4] = mx;
        }
        signalCnt(&c_red2);
        return;
    }
    if (tb == 7) {
        // combine row-dot halves -> g_resp[0..2046]
        waitCnt(&c_red, MIXBLK);
        for (int r = t; r < XS - 1; r += 256) {
            int ch = r >> 5, idx = r & 31;
            g_resp[r] = g_respPart[ch][0][idx] + g_respPart[ch][1][idx];
        }
        return;
    }
    {
        // dots: |mix_x|^2, mix_x.inpt, |inpt|^2
        waitCnt(&c_red2, 7);
        const float4* mx4 = reinterpret_cast<const float4*>(g_mix_x);
        float dxx = 0.0f, dxi = 0.0f, dii = 0.0f;
        for (int c4 = t; c4 < NV4; c4 += 256) {
            float4 m = mx4[c4];
            float4 p = inpt4(c4, x4, y4, z4);
            dxx = fmaf(m.x, m.x, dxx); dxx = fmaf(m.y, m.y, dxx);
            dxx = fmaf(m.z, m.z, dxx); dxx = fmaf(m.w, m.w, dxx);
            dxi = fmaf(m.x, p.x, dxi); dxi = fmaf(m.y, p.y, dxi);
            dxi = fmaf(m.z, p.z, dxi); dxi = fmaf(m.w, p.w, dxi);
            dii = fmaf(p.x, p.x, dii); dii = fmaf(p.y, p.y, dii);
            dii = fmaf(p.z, p.z, dii); dii = fmaf(p.w, p.w, dii);
        }
        float sxx = blockReduceSumB(dxx);
        float sxi = blockReduceSumB(dxi);
        float sii = blockReduceSumB(dii);
        if (t == 0) { g_dots[0] = sxx; g_dots[1] = sxi; g_dots[2] = sii; }
    }
}

// ---------------- K3: selection + mixes + all row updates ----------------
__global__ void k_post(const float* __restrict__ ages, const float4* __restrict__ neu4,
                       const float4* __restrict__ x4, const float4* __restrict__ y4,
                       const float4* __restrict__ z4,
                       float* __restrict__ out_z, float* __restrict__ out_final,
                       float* __restrict__ out_ages, float* __restrict__ out_neu) {
    int t = threadIdx.x;      // 0..255
    int b = blockIdx.x;

    // ======== x update blocks (bulk of work) ========
    if (b >= B_XU0 && b < B_YZ0) {
        waitCnt(&c_x, 1);
        int r0 = (b - B_XU0) * 4;
        float invdx = g_inv_dx;
        float dxx = g_dots[0], dxi = g_dots[1], dii = g_dots[2];
        if (b == B_YZ0 - 1 && t == 0)
            out_final[XS - 1] = g_resp[XS - 1] * invdx;
        const float4* mxp = reinterpret_cast<const float4*>(g_mix_x);
#pragma unroll 1
        for (int rr = 0; rr < 4; rr++) {
            int r = r0 + rr;
            if (r >= XS - 1) break;   // uniform across block
            float a = __ldg(&ages[r]);
            float rsp = g_resp[r];
            if (t == 0) {
                out_final[r] = rsp * invdx;
                out_ages[r]  = a + 1.0f;
            }
            float s = rsp * invdx / a;
            float ssq = dxx + 2.0f * s * dxi + s * s * dii;
            float inv = 1.0f / (sqrtf(ssq) + 1e-12f);
            float si = s * inv;
            float4* dst = reinterpret_cast<float4*>(out_neu) + (size_t)r * NV4;
#pragma unroll
            for (int j = 0; j < 7; j++) {
                int c4 = t + j * 256;
                if (c4 < NV4) {
                    float4 iv = inpt4(c4, x4, y4, z4), mv = mxp[c4];
                    float4 o;
                    o.x = fmaf(si, iv.x, mv.x * inv);
                    o.y = fmaf(si, iv.y, mv.y * inv);
                    o.z = fmaf(si, iv.z, mv.z * inv);
                    o.w = fmaf(si, iv.w, mv.w * inv);
                    __stcs(dst + c4, o);
                }
            }
        }
        return;
    }

    // ======== yz update blocks ========
    if (b >= B_YZ0) {
        waitCnt(&c_myz, 7);
        int bb = b - B_YZ0;
        int r; float val; const float4* mix;
        if (bb < TK) { r = g_yrow[bb]; val = g_yval[bb]; mix = reinterpret_cast<const float4*>(g_mix_y); }
        else         { r = g_zrow[bb - TK]; val = g_zval[bb - TK]; mix = reinterpret_cast<const float4*>(g_mix_z); }
        float s = val / __ldg(&ages[r]);
        float4 v[7];
        float ssq = 0.0f;
#pragma unroll
        for (int j = 0; j < 7; j++) {
            int c4 = t + j * 256;
            if (c4 < NV4) {
                float4 iv = inpt4(c4, x4, y4, z4), mv = mix[c4];
                float4 vv;
                vv.x = fmaf(s, iv.x, mv.x);
                vv.y = fmaf(s, iv.y, mv.y);
                vv.z = fmaf(s, iv.z, mv.z);
                vv.w = fmaf(s, iv.w, mv.w);
                v[j] = vv;
                ssq = fmaf(vv.x, vv.x, ssq);
                ssq = fmaf(vv.y, vv.y, ssq);
                ssq = fmaf(vv.z, vv.z, ssq);
                ssq = fmaf(vv.w, vv.w, ssq);
            }
        }
        float tot = blockReduceSumB(ssq);
        float inv = 1.0f / (sqrtf(tot) + 1e-12f);
        float4* dst = reinterpret_cast<float4*>(out_neu) + (size_t)r * NV4;
#pragma unroll
        for (int j = 0; j < 7; j++) {
            int c4 = t + j * 256;
            if (c4 < NV4) {
                float4 o = v[j];
                o.x *= inv; o.y *= inv; o.z *= inv; o.w *= inv;
                __stcs(dst + c4, o);
            }
        }
        return;
    }

    // ======== selection blocks ========
    if (b < B_Z) {
        // y candidates: key-rank over 256
        __shared__ u64 sk[256];
        int w = b - B_YC0;
        int row = XS + w * 256 + t;
        u64 key = makeKey(g_resp[row], row);
        sk[t] = key;
        __syncthreads();
        int rank = 0;
#pragma unroll 8
        for (int j = 0; j < 256; j++) rank += (sk[j] > key);
        if (rank < TK + 1) g_ckey[w][rank] = key;
        signalCnt(&c_yc);
        return;
    }

    if (b == B_Z) {
        __shared__ u64   zk[ZS];
        __shared__ float s_zv[ZTK + 1];
        __shared__ int   s_zr[ZTK + 1];
        if (t < ZS) {
            int row = XS + NN + t;
            zk[t] = makeKey(g_resp[row], row);
        }
        __syncthreads();
        if (t < ZS) {
            u64 key = zk[t];
            int rank = 0;
#pragma unroll
            for (int j = 0; j < ZS; j++) rank += (zk[j] > key);
            if (rank < ZTK + 1) {
                float v = keyVal(key); int row = keyRow(key);
                s_zv[rank] = v; s_zr[rank] = row;
                g_zval[rank] = v; g_zrow[rank] = row;
            }
        }
        __syncthreads();
        if (t < ZTK) {
            float zvL = s_zv[ZTK];
            float dz = 1.0f / (s_zv[0] - zvL);
            int r = s_zr[t];
            float f = (s_zv[t] - zvL) * dz;
            out_final[r] = f;
            out_z[r - (XS + NN)] = f;
            out_ages[r] = ages[r] + 1.0f;
        }
        signalCnt(&c_z);
        return;
    }

    if (b == B_XM) {
        __shared__ float s_xv[8];
        __shared__ int   s_xnz[8];
        int lane = t & 31;
        int wid  = t >> 5;
        float bv = -FLT_MAX; int nz = 0;
#pragma unroll
        for (int j = 0; j < 8; j++) {
            float v = g_resp[t + j * 256];
            bv = fmaxf(bv, v);
            nz |= (v != 0.0f);
        }
#pragma unroll
        for (int o = 16; o > 0; o >>= 1) {
            bv  = fmaxf(bv, __shfl_down_sync(0xffffffffu, bv, o));
            nz |= __shfl_down_sync(0xffffffffu, nz, o);
        }
        if (lane == 0) { s_xv[wid] = bv; s_xnz[wid] = nz; }
        __syncthreads();
        if (t == 0) {
            float m = s_xv[0]; int z2 = s_xnz[0];
#pragma unroll
            for (int w2 = 1; w2 < 8; w2++) { m = fmaxf(m, s_xv[w2]); z2 |= s_xnz[w2]; }
            float tx = z2 ? 0.0f : 1.0f;
            g_inv_dx = 1.0f / (m + EPSF * tx * RNDF);
        }
        signalCnt(&c_x);
        return;
    }

    if (b == B_YM) {
        __shared__ u64   s_k[NCAND];
        __shared__ float s_yv[TK + 1];
        __shared__ int   s_yr[TK + 1];
        waitCnt(&c_yc, YBLK);
        s_k[t] = ((const u64*)g_ckey)[t];
        if (t < NCAND - 256) s_k[256 + t] = ((const u64*)g_ckey)[256 + t];
        __syncthreads();
#pragma unroll 1
        for (int pass = 0; pass < 2; pass++) {
            int idx = t + pass * 256;
            if (idx < NCAND) {
                u64 key = s_k[idx];
                int rank = 0;
#pragma unroll 8
                for (int j = 0; j < NCAND; j++) rank += (s_k[j] > key);
                if (rank < TK + 1) {
                    float v = keyVal(key); int row = keyRow(key);
                    s_yv[rank] = v; s_yr[rank] = row;
                    g_yval[rank] = v; g_yrow[rank] = row;
                }
            }
        }
        __syncthreads();
        if (t < 32) {
            float yvL = s_yv[TK];
            bool tie = (t < TK) && (s_yv[t] == yvL);
            u32 bal = __ballot_sync(0xffffffffu, tie);
            float ty = bal ? 1.0f : 0.0f;
            if (t < TK) {
                float dy = 1.0f / (s_yv[0] - yvL + EPSF * ty * RNDF);
                int r = s_yr[t];
                out_final[r] = (s_yv[t] - yvL) * dy;
                out_ages[r]  = ages[r] + 1.0f;
            }
        }
        signalCnt(&c_y);
        return;
    }

    // ---- b in B_MYZ0..B_MYZ0+6: mix_y / mix_z ----
    {
        waitCnt(&c_y, 1);
        waitCnt(&c_z, 1);
        int c4 = (b - B_MYZ0) * 256 + t;
        if (c4 < NV4) {
            float4 my = {0, 0, 0, 0};
#pragma unroll
            for (int k = 0; k < TK; k++) {
                int r = g_yrow[k];
                float ag = __ldg(&ages[r]);
                float w = (ag - 1.0f) / ag;
                float4 v = __ldg(&neu4[(size_t)r * NV4 + c4]);
                my.x = fmaf(w, v.x, my.x); my.y = fmaf(w, v.y, my.y);
                my.z = fmaf(w, v.z, my.z); my.w = fmaf(w, v.w, my.w);
            }
            reinterpret_cast<float4*>(g_mix_y)[c4] = my;

            float4 mz = {0, 0, 0, 0};
#pragma unroll
            for (int k = 0; k < ZTK; k++) {
                int r = g_zrow[k];
                float ag = __ldg(&ages[r]);
                float w = (ag - 1.0f) / ag;
                float4 v = __ldg(&neu4[(size_t)r * NV4 + c4]);
                mz.x = fmaf(w, v.x, mz.x); mz.y = fmaf(w, v.y, mz.y);
                mz.z = fmaf(w, v.z, mz.z); mz.w = fmaf(w, v.w, mz.w);
            }
            reinterpret_cast<float4*>(g_mix_z)[c4] = mz;
        }
        signalCnt(&c_myz);
        return;
    }
}

// ---------------- launch ----------------
extern "C" void kernel_launch(void* const* d_in, const int* in_sizes, int n_in,
                              void* d_out, int out_size) {
    (void)in_sizes; (void)n_in; (void)out_size;
    const float* x       = (const float*)d_in[0];
    const float* z       = (const float*)d_in[1];
    const float* yresp   = (const float*)d_in[2];
    const float* neurons = (const float*)d_in[3];
    const float* ages    = (const float*)d_in[4];

    float* out       = (float*)d_out;
    float* out_z     = out;                                // 64
    float* out_final = out + ZS;                           // 6208
    float* out_neu   = out + ZS + DD;                      // 6208*6208
    float* out_ages  = out + ZS + DD + (size_t)DD * DD;    // 6208

    k_init<<<8, 256>>>(ages, out_z, out_final, out_ages);
    k_main<<<NMAIN, 256>>>((const float4*)neurons, ages,
                           (const float4*)x, (const float4*)yresp, (const float4*)z,
                           out_neu);
    k_post<<<NPOST, 256>>>(ages, (const float4*)neurons,
                           (const float4*)x, (const float4*)yresp, (const float4*)z,
                           out_z, out_final, out_ages, out_neu);
}

// round 12
// speedup vs baseline: 1.0699x; 1.0699x over previous
#include <cuda_runtime.h>
#include <math.h>
#include <float.h>

#define XS 2048
#define NN 4096
#define ZS 64
#define DD 6208
#define NV4 1552          // DD/4
#define TK 16
#define ZTK 8
#define EPSF 1e-9f
#define RNDF 0.5f
#define NCHUNK 64         // 32 rows per chunk
#define MIXBLK 128        // NCHUNK * 2 column-halves
#define HALF4 776         // NV4/2
#define YBLK 16
#define NCAND (YBLK * (TK + 1))   // 272

// k_main block layout: [0,7) reduce, 7 dots, [8,136) mixx, [136,136+DD) matvec
#define MB_RED0  0
#define MB_DOTS  7
#define MB_MIX0  8
#define MB_MV0   136
#define NMAIN    (MB_MV0 + DD)

// k_post block roles
#define B_YC0   0         // 16 blocks: y candidates (+ zero/copy y range)
#define B_Z     16        // z top-9 + finals (+ zero/copy z range, reset main ctrs)
#define B_XM    17        // x max -> inv_dx (+ age copy row XS-1)
#define B_YM    18        // y merge
#define B_MYZ0  19        // 7 blocks: mix_y/mix_z
#define B_XU0   26        // 512 blocks: x updates
#define B_YZ0   538       // 24 blocks: yz updates
#define NPOST   562

typedef unsigned long long u64;
typedef unsigned int u32;

// ---------------- device scratch (no allocations allowed) ----------------
__device__ __align__(16) float g_resp[DD];
__device__ __align__(16) float g_mix_x[DD];
__device__ __align__(16) float g_mix_y[DD];
__device__ __align__(16) float g_mix_z[DD];
__device__ float4 g_part4[NCHUNK][NV4];     // mix_x partials
__device__ u64   g_ckey[YBLK][TK + 1];
__device__ float g_yval[TK + 1];
__device__ int   g_yrow[TK + 1];
__device__ float g_zval[ZTK + 1];
__device__ int   g_zrow[ZTK + 1];
__device__ float g_inv_dx;
__device__ float g_dots[3];                 // |mix_x|^2, mix_x.inpt, |inpt|^2
// dependency counters (zero-init; cross-kernel reset scheme)
__device__ int c_red, c_red2;               // k_main internal (reset by k_post B_Z)
__device__ int c_yc, c_y, c_z, c_x, c_myz;  // k_post internal (reset by k_main dots block)

// ---------------- helpers ----------------
__device__ __forceinline__ float blockReduceSumB(float v) {
    __shared__ float red[32];
    __shared__ float bcast;
    int lane = threadIdx.x & 31;
    int wid  = threadIdx.x >> 5;
    int nw   = blockDim.x >> 5;
#pragma unroll
    for (int o = 16; o > 0; o >>= 1) v += __shfl_down_sync(0xffffffffu, v, o);
    if (lane == 0) red[wid] = v;
    __syncthreads();
    if (wid == 0) {
        float x = (lane < nw) ? red[lane] : 0.0f;
#pragma unroll
        for (int o = 16; o > 0; o >>= 1) x += __shfl_down_sync(0xffffffffu, x, o);
        if (lane == 0) bcast = x;
    }
    __syncthreads();
    return bcast;
}

__device__ __forceinline__ u64 makeKey(float v, int row) {
    u32 u = __float_as_uint(v);
    u = (u & 0x80000000u) ? ~u : (u | 0x80000000u);
    return ((u64)u << 32) | (u32)(~row);
}
__device__ __forceinline__ float keyVal(u64 k) {
    u32 u = (u32)(k >> 32);
    u32 bits = (u & 0x80000000u) ? (u ^ 0x80000000u) : ~u;
    return __uint_as_float(bits);
}
__device__ __forceinline__ int keyRow(u64 k) { return (int)~((u32)k); }

// inline input vector: select from x / y_response / z
__device__ __forceinline__ float4 inpt4(int c4, const float4* __restrict__ x4,
                                        const float4* __restrict__ y4,
                                        const float4* __restrict__ z4) {
    if (c4 < 512)  return __ldg(x4 + c4);
    if (c4 < 1536) return __ldg(y4 + (c4 - 512));
    return __ldg(z4 + (c4 - 1536));
}

__device__ __forceinline__ void signalCnt(int* c) {
    __threadfence();
    __syncthreads();
    if (threadIdx.x == 0) atomicAdd(c, 1);
}
__device__ __forceinline__ void waitCnt(int* c, int target) {
    if (threadIdx.x == 0) {
        while (atomicAdd(c, 0) < target) __nanosleep(64);
    }
    __syncthreads();
}

// ---------------- K1: mixx partials + matvec/copy + reduce/dots tail ----------------
__global__ void k_main(const float4* __restrict__ neu4, const float* __restrict__ ages,
                       const float4* __restrict__ x4, const float4* __restrict__ y4,
                       const float4* __restrict__ z4, float* __restrict__ out_neu) {
    int t = threadIdx.x;
    int b = blockIdx.x;

    if (b < MB_DOTS) {
        // ---- mix_x reduce (waits for all 128 mixx blocks; co-resident wave 1) ----
        waitCnt(&c_red, MIXBLK);
        int c4 = b * 256 + t;
        if (c4 < NV4) {
            float4 mx = {0, 0, 0, 0};
#pragma unroll
            for (int ch = 0; ch < NCHUNK; ch++) {
                float4 p = g_part4[ch][c4];
                mx.x += p.x; mx.y += p.y; mx.z += p.z; mx.w += p.w;
            }
            reinterpret_cast<float4*>(g_mix_x)[c4] = mx;
        }
        signalCnt(&c_red2);
        return;
    }

    if (b == MB_DOTS) {
        // reset k_post's counters (previous replay's k_post finished by stream order)
        if (t == 0) { c_yc = 0; c_y = 0; c_z = 0; c_x = 0; c_myz = 0; }
        waitCnt(&c_red2, 7);
        const float4* mx4 = reinterpret_cast<const float4*>(g_mix_x);
        float dxx = 0.0f, dxi = 0.0f, dii = 0.0f;
        for (int c4 = t; c4 < NV4; c4 += 256) {
            float4 m = mx4[c4];
            float4 p = inpt4(c4, x4, y4, z4);
            dxx = fmaf(m.x, m.x, dxx); dxx = fmaf(m.y, m.y, dxx);
            dxx = fmaf(m.z, m.z, dxx); dxx = fmaf(m.w, m.w, dxx);
            dxi = fmaf(m.x, p.x, dxi); dxi = fmaf(m.y, p.y, dxi);
            dxi = fmaf(m.z, p.z, dxi); dxi = fmaf(m.w, p.w, dxi);
            dii = fmaf(p.x, p.x, dii); dii = fmaf(p.y, p.y, dii);
            dii = fmaf(p.z, p.z, dii); dii = fmaf(p.w, p.w, dii);
        }
        float sxx = blockReduceSumB(dxx);
        float sxi = blockReduceSumB(dxi);
        float sii = blockReduceSumB(dii);
        if (t == 0) { g_dots[0] = sxx; g_dots[1] = sxi; g_dots[2] = sii; }
        return;
    }

    if (b < MB_MV0) {
        // ---- mix_x partials: chunk of 32 rows, one column half ----
        int bb = b - MB_MIX0;
        int chunk = bb >> 1;
        int half  = bb & 1;
        int r0 = chunk * 32;
        int r1 = min(r0 + 32, XS - 1);
        int cbase = half * HALF4;
        float4 acc0 = {0,0,0,0}, acc1 = {0,0,0,0}, acc2 = {0,0,0,0}, acc3 = {0,0,0,0};
        int c0 = cbase + t;
        int c1 = cbase + 256 + t;
        int c2 = cbase + 512 + t;
        int c3 = cbase + 768 + t;
        bool v3 = (768 + t) < HALF4;
#pragma unroll 1
        for (int r = r0; r < r1; r++) {
            float ag = __ldg(&ages[r]);
            float w = (ag - 1.0f) / ag;
            const float4* rowp = neu4 + (size_t)r * NV4;
            float4 a  = __ldg(rowp + c0);
            float4 bq = __ldg(rowp + c1);
            float4 cq = __ldg(rowp + c2);
            float4 dq = v3 ? __ldg(rowp + c3) : make_float4(0, 0, 0, 0);
            acc0.x = fmaf(w, a.x, acc0.x);  acc0.y = fmaf(w, a.y, acc0.y);
            acc0.z = fmaf(w, a.z, acc0.z);  acc0.w = fmaf(w, a.w, acc0.w);
            acc1.x = fmaf(w, bq.x, acc1.x); acc1.y = fmaf(w, bq.y, acc1.y);
            acc1.z = fmaf(w, bq.z, acc1.z); acc1.w = fmaf(w, bq.w, acc1.w);
            acc2.x = fmaf(w, cq.x, acc2.x); acc2.y = fmaf(w, cq.y, acc2.y);
            acc2.z = fmaf(w, cq.z, acc2.z); acc2.w = fmaf(w, cq.w, acc2.w);
            acc3.x = fmaf(w, dq.x, acc3.x); acc3.y = fmaf(w, dq.y, acc3.y);
            acc3.z = fmaf(w, dq.z, acc3.z); acc3.w = fmaf(w, dq.w, acc3.w);
        }
        g_part4[chunk][c0] = acc0;
        g_part4[chunk][c1] = acc1;
        g_part4[chunk][c2] = acc2;
        if (v3) g_part4[chunk][c3] = acc3;
        signalCnt(&c_red);
        return;
    }

    // ---- matvec row + fused copy (skip rows < XS-1, rewritten later) ----
    int row = b - MB_MV0;
    const float4* src = neu4 + (size_t)row * NV4;
    float4* dst = reinterpret_cast<float4*>(out_neu) + (size_t)row * NV4;
    float acc = 0.0f;
    bool docopy = (row >= XS - 1);
#pragma unroll
    for (int j = 0; j < 7; j++) {
        int c = t + j * 256;
        if (c < NV4) {
            float4 v = __ldg(src + c);
            float4 w = inpt4(c, x4, y4, z4);
            acc = fmaf(v.x, w.x, acc);
            acc = fmaf(v.y, w.y, acc);
            acc = fmaf(v.z, w.z, acc);
            acc = fmaf(v.w, w.w, acc);
            if (docopy) __stcs(dst + c, v);
        }
    }
    float tot = blockReduceSumB(acc);
    if (t == 0) g_resp[row] = tot;
}

// ---------------- K2: selection + init-work + mixes + all row updates ----------------
__global__ void k_post(const float* __restrict__ ages, const float4* __restrict__ neu4,
                       const float4* __restrict__ x4, const float4* __restrict__ y4,
                       const float4* __restrict__ z4,
                       float* __restrict__ out_z, float* __restrict__ out_final,
                       float* __restrict__ out_ages, float* __restrict__ out_neu) {
    int t = threadIdx.x;      // 0..255
    int b = blockIdx.x;

    // ======== x update blocks (bulk of work) ========
    if (b >= B_XU0 && b < B_YZ0) {
        waitCnt(&c_x, 1);
        int r0 = (b - B_XU0) * 4;
        float invdx = g_inv_dx;
        float dxx = g_dots[0], dxi = g_dots[1], dii = g_dots[2];
        if (b == B_YZ0 - 1 && t == 0)
            out_final[XS - 1] = g_resp[XS - 1] * invdx;   // last x row: final only
        const float4* mxp = reinterpret_cast<const float4*>(g_mix_x);
#pragma unroll 1
        for (int rr = 0; rr < 4; rr++) {
            int r = r0 + rr;
            if (r >= XS - 1) break;   // uniform across block
            float a = __ldg(&ages[r]);
            float rsp = g_resp[r];
            if (t == 0) {
                out_final[r] = rsp * invdx;
                out_ages[r]  = a + 1.0f;
            }
            float s = rsp * invdx / a;
            float ssq = dxx + 2.0f * s * dxi + s * s * dii;
            float inv = 1.0f / (sqrtf(ssq) + 1e-12f);
            float si = s * inv;
            float4* dst = reinterpret_cast<float4*>(out_neu) + (size_t)r * NV4;
#pragma unroll
            for (int j = 0; j < 7; j++) {
                int c4 = t + j * 256;
                if (c4 < NV4) {
                    float4 iv = inpt4(c4, x4, y4, z4), mv = mxp[c4];
                    float4 o;
                    o.x = fmaf(si, iv.x, mv.x * inv);
                    o.y = fmaf(si, iv.y, mv.y * inv);
                    o.z = fmaf(si, iv.z, mv.z * inv);
                    o.w = fmaf(si, iv.w, mv.w * inv);
                    __stcs(dst + c4, o);
                }
            }
        }
        return;
    }

    // ======== yz update blocks ========
    if (b >= B_YZ0) {
        waitCnt(&c_myz, 7);
        int bb = b - B_YZ0;
        int r; float val; const float4* mix;
        if (bb < TK) { r = g_yrow[bb]; val = g_yval[bb]; mix = reinterpret_cast<const float4*>(g_mix_y); }
        else         { r = g_zrow[bb - TK]; val = g_zval[bb - TK]; mix = reinterpret_cast<const float4*>(g_mix_z); }
        float s = val / __ldg(&ages[r]);
        float4 v[7];
        float ssq = 0.0f;
#pragma unroll
        for (int j = 0; j < 7; j++) {
            int c4 = t + j * 256;
            if (c4 < NV4) {
                float4 iv = inpt4(c4, x4, y4, z4), mv = mix[c4];
                float4 vv;
                vv.x = fmaf(s, iv.x, mv.x);
                vv.y = fmaf(s, iv.y, mv.y);
                vv.z = fmaf(s, iv.z, mv.z);
                vv.w = fmaf(s, iv.w, mv.w);
                v[j] = vv;
                ssq = fmaf(vv.x, vv.x, ssq);
                ssq = fmaf(vv.y, vv.y, ssq);
                ssq = fmaf(vv.z, vv.z, ssq);
                ssq = fmaf(vv.w, vv.w, ssq);
            }
        }
        float tot = blockReduceSumB(ssq);
        float inv = 1.0f / (sqrtf(tot) + 1e-12f);
        float4* dst = reinterpret_cast<float4*>(out_neu) + (size_t)r * NV4;
#pragma unroll
        for (int j = 0; j < 7; j++) {
            int c4 = t + j * 256;
            if (c4 < NV4) {
                float4 o = v[j];
                o.x *= inv; o.y *= inv; o.z *= inv; o.w *= inv;
                __stcs(dst + c4, o);
            }
        }
        return;
    }

    // ======== selection / init blocks ========
    if (b < B_Z) {
        // ---- y candidates + zero out_final / copy out_ages for this y range ----
        __shared__ u64 sk[256];
        int w = b - B_YC0;
        int row = XS + w * 256 + t;
        out_final[row] = 0.0f;
        out_ages[row]  = __ldg(&ages[row]);
        u64 key = makeKey(g_resp[row], row);
        sk[t] = key;
        __syncthreads();
        int rank = 0;
#pragma unroll 8
        for (int j = 0; j < 256; j++) rank += (sk[j] > key);
        if (rank < TK + 1) g_ckey[w][rank] = key;
        signalCnt(&c_yc);
        return;
    }

    if (b == B_Z) {
        // ---- z range init + z top-9 + finals; also reset k_main counters ----
        __shared__ u64   zk[ZS];
        __shared__ float s_zv[ZTK + 1];
        __shared__ int   s_zr[ZTK + 1];
        if (t == 0) { c_red = 0; c_red2 = 0; }   // for next replay's k_main
        if (t < ZS) {
            int row = XS + NN + t;
            out_z[t] = 0.0f;
            out_final[row] = 0.0f;
            out_ages[row]  = __ldg(&ages[row]);
            zk[t] = makeKey(g_resp[row], row);
        }
        __syncthreads();
        if (t < ZS) {
            u64 key = zk[t];
            int rank = 0;
#pragma unroll
            for (int j = 0; j < ZS; j++) rank += (zk[j] > key);
            if (rank < ZTK + 1) {
                float v = keyVal(key); int row = keyRow(key);
                s_zv[rank] = v; s_zr[rank] = row;
                g_zval[rank] = v; g_zrow[rank] = row;
            }
        }
        __syncthreads();
        if (t < ZTK) {
            float zvL = s_zv[ZTK];
            float dz = 1.0f / (s_zv[0] - zvL);
            int r = s_zr[t];
            float f = (s_zv[t] - zvL) * dz;
            out_final[r] = f;
            out_z[r - (XS + NN)] = f;
            out_ages[r] = __ldg(&ages[r]) + 1.0f;
        }
        signalCnt(&c_z);
        return;
    }

    if (b == B_XM) {
        // ---- x max + nonzero -> g_inv_dx; copy age of row XS-1 ----
        __shared__ float s_xv[8];
        __shared__ int   s_xnz[8];
        int lane = t & 31;
        int wid  = t >> 5;
        if (t == 0) out_ages[XS - 1] = __ldg(&ages[XS - 1]);
        float bv = -FLT_MAX; int nz = 0;
#pragma unroll
        for (int j = 0; j < 8; j++) {
            float v = g_resp[t + j * 256];
            bv = fmaxf(bv, v);
            nz |= (v != 0.0f);
        }
#pragma unroll
        for (int o = 16; o > 0; o >>= 1) {
            bv  = fmaxf(bv, __shfl_down_sync(0xffffffffu, bv, o));
            nz |= __shfl_down_sync(0xffffffffu, nz, o);
        }
        if (lane == 0) { s_xv[wid] = bv; s_xnz[wid] = nz; }
        __syncthreads();
        if (t == 0) {
            float m = s_xv[0]; int z2 = s_xnz[0];
#pragma unroll
            for (int w2 = 1; w2 < 8; w2++) { m = fmaxf(m, s_xv[w2]); z2 |= s_xnz[w2]; }
            float tx = z2 ? 0.0f : 1.0f;
            g_inv_dx = 1.0f / (m + EPSF * tx * RNDF);
        }
        signalCnt(&c_x);
        return;
    }

    if (b == B_YM) {
        // ---- y merge: rank over 272 candidates + finals ----
        __shared__ u64   s_k[NCAND];
        __shared__ float s_yv[TK + 1];
        __shared__ int   s_yr[TK + 1];
        waitCnt(&c_yc, YBLK);
        s_k[t] = ((const u64*)g_ckey)[t];
        if (t < NCAND - 256) s_k[256 + t] = ((const u64*)g_ckey)[256 + t];
        __syncthreads();
#pragma unroll 1
        for (int pass = 0; pass < 2; pass++) {
            int idx = t + pass * 256;
            if (idx < NCAND) {
                u64 key = s_k[idx];
                int rank = 0;
#pragma unroll 8
                for (int j = 0; j < NCAND; j++) rank += (s_k[j] > key);
                if (rank < TK + 1) {
                    float v = keyVal(key); int row = keyRow(key);
                    s_yv[rank] = v; s_yr[rank] = row;
                    g_yval[rank] = v; g_yrow[rank] = row;
                }
            }
        }
        __syncthreads();
        if (t < 32) {
            float yvL = s_yv[TK];
            bool tie = (t < TK) && (s_yv[t] == yvL);
            u32 bal = __ballot_sync(0xffffffffu, tie);
            float ty = bal ? 1.0f : 0.0f;
            if (t < TK) {
                float dy = 1.0f / (s_yv[0] - yvL + EPSF * ty * RNDF);
                int r = s_yr[t];
                out_final[r] = (s_yv[t] - yvL) * dy;
                out_ages[r]  = __ldg(&ages[r]) + 1.0f;
            }
        }
        signalCnt(&c_y);
        return;
    }

    // ---- b in B_MYZ0..B_MYZ0+6: mix_y / mix_z ----
    {
        waitCnt(&c_y, 1);
        waitCnt(&c_z, 1);
        int c4 = (b - B_MYZ0) * 256 + t;
        if (c4 < NV4) {
            float4 my = {0, 0, 0, 0};
#pragma unroll
            for (int k = 0; k < TK; k++) {
                int r = g_yrow[k];
                float ag = __ldg(&ages[r]);
                float w = (ag - 1.0f) / ag;
                float4 v = __ldg(&neu4[(size_t)r * NV4 + c4]);
                my.x = fmaf(w, v.x, my.x); my.y = fmaf(w, v.y, my.y);
                my.z = fmaf(w, v.z, my.z); my.w = fmaf(w, v.w, my.w);
            }
            reinterpret_cast<float4*>(g_mix_y)[c4] = my;

            float4 mz = {0, 0, 0, 0};
#pragma unroll
            for (int k = 0; k < ZTK; k++) {
                int r = g_zrow[k];
                float ag = __ldg(&ages[r]);
                float w = (ag - 1.0f) / ag;
                float4 v = __ldg(&neu4[(size_t)r * NV4 + c4]);
                mz.x = fmaf(w, v.x, mz.x); mz.y = fmaf(w, v.y, mz.y);
                mz.z = fmaf(w, v.z, mz.z); mz.w = fmaf(w, v.w, mz.w);
            }
            reinterpret_cast<float4*>(g_mix_z)[c4] = mz;
        }
        signalCnt(&c_myz);
        return;
    }
}

// ---------------- launch ----------------
extern "C" void kernel_launch(void* const* d_in, const int* in_sizes, int n_in,
                              void* d_out, int out_size) {
    (void)in_sizes; (void)n_in; (void)out_size;
    const float* x       = (const float*)d_in[0];
    const float* z       = (const float*)d_in[1];
    const float* yresp   = (const float*)d_in[2];
    const float* neurons = (const float*)d_in[3];
    const float* ages    = (const float*)d_in[4];

    float* out       = (float*)d_out;
    float* out_z     = out;                                // 64
    float* out_final = out + ZS;                           // 6208
    float* out_neu   = out + ZS + DD;                      // 6208*6208
    float* out_ages  = out + ZS + DD + (size_t)DD * DD;    // 6208

    k_main<<<NMAIN, 256>>>((const float4*)neurons, ages,
                           (const float4*)x, (const float4*)yresp, (const float4*)z,
                           out_neu);
    k_post<<<NPOST, 256>>>(ages, (const float4*)neurons,
                           (const float4*)x, (const float4*)yresp, (const float4*)z,
                           out_z, out_final, out_ages, out_neu);
}